// round 2
// baseline (speedup 1.0000x reference)
#include <cuda_runtime.h>

#define NFILT 384      // 3 banks * 128 filters
#define NPTS  2048     // B*H'*W' = 2*32*32
#define KB    96
#define NBINS 97

// ---- scratch (static device globals; no allocation anywhere) ----
__device__ float g_x[NFILT * NPTS];
__device__ float g_y[NFILT * NPTS];
__device__ float g_tau[NFILT];
__device__ float g_phat[NFILT * 4 * NBINS];
__device__ float g_loss[NFILT];

__device__ __forceinline__ float ex2f(float x) {
    float r; asm("ex2.approx.f32 %0, %1;" : "=f"(r) : "f"(x)); return r;
}
__device__ __forceinline__ float rcpf(float x) {
    float r; asm("rcp.approx.f32 %0, %1;" : "=f"(r) : "f"(x)); return r;
}

// ============================================================
// Stage 1: direct conv, stride 2, zero padding, per-channel
// shared tile padded to 72x72 (pad 3 >= max k//2) -> no bounds
// checks in the tap loop.
// grid: 1536 = 3 banks * 2 srcs * 128 filters * 2 batches
// ============================================================
template <int KS>
__device__ __forceinline__ void conv_accum(const float* Xs, const float* Wc, float* acc) {
    const int P = KS / 2;
    int t = threadIdx.x;
#pragma unroll
    for (int r = 0; r < 4; r++) {
        int idx = t + r * 256;
        int oy = idx >> 5, ox = idx & 31;
        const float* xb = Xs + (2 * oy + 3 - P) * 72 + (2 * ox + 3 - P);
        float a = acc[r];
#pragma unroll
        for (int u = 0; u < KS; u++)
#pragma unroll
            for (int v = 0; v < KS; v++)
                a = fmaf(Wc[u * KS + v], xb[u * 72 + v], a);
        acc[r] = a;
    }
}

__global__ void __launch_bounds__(256) conv_kernel(
    const float* __restrict__ Xg, const float* __restrict__ Xd,
    const float* __restrict__ W3, const float* __restrict__ W5,
    const float* __restrict__ W7) {
    __shared__ float Xs[72 * 72];
    __shared__ float Ws[3 * 49];

    int bx   = blockIdx.x;
    int bank = bx >> 9;          // 0..2
    int rem  = bx & 511;
    int src  = rem >> 8;         // 0 = Xg, 1 = Xd
    int l    = (rem >> 1) & 127;
    int b    = rem & 1;

    const float* X = (src ? Xd : Xg) + b * 12288;
    const float* W;
    int KS;
    if (bank == 0)      { W = W3; KS = 3; }
    else if (bank == 1) { W = W5; KS = 5; }
    else                { W = W7; KS = 7; }
    int wsz = 3 * KS * KS;

    // zero borders once; interior rewritten per channel
    for (int i = threadIdx.x; i < 72 * 72; i += 256) Xs[i] = 0.f;
    for (int i = threadIdx.x; i < wsz; i += 256) Ws[i] = W[l * wsz + i];

    float acc[4] = {0.f, 0.f, 0.f, 0.f};
    for (int c = 0; c < 3; c++) {
        __syncthreads();
        for (int i = threadIdx.x; i < 4096; i += 256) {
            int r = i >> 6, col = i & 63;
            Xs[(r + 3) * 72 + (col + 3)] = X[c * 4096 + i];
        }
        __syncthreads();
        const float* Wc = Ws + c * KS * KS;
        if (bank == 0)      conv_accum<3>(Xs, Wc, acc);
        else if (bank == 1) conv_accum<5>(Xs, Wc, acc);
        else                conv_accum<7>(Xs, Wc, acc);
    }

    float* outp = (src ? g_y : g_x) + (bank * 128 + l) * NPTS + b * 1024;
#pragma unroll
    for (int r = 0; r < 4; r++) outp[threadIdx.x + r * 256] = acc[r];
}

// ============================================================
// Stage 2: per-filter tau = scale*(std(y, ddof=1)+1e-6)+1e-4
// ============================================================
__global__ void __launch_bounds__(256) tau_kernel() {
    int f = blockIdx.x;
    const float* y = g_y + f * NPTS;
    float s = 0.f, ss = 0.f;
    for (int i = threadIdx.x; i < NPTS; i += 256) {
        float v = y[i];
        s += v;
        ss = fmaf(v, v, ss);
    }
    __shared__ float sh1[8], sh2[8];
    for (int o = 16; o > 0; o >>= 1) {
        s  += __shfl_down_sync(0xffffffffu, s, o);
        ss += __shfl_down_sync(0xffffffffu, ss, o);
    }
    int w = threadIdx.x >> 5, lane = threadIdx.x & 31;
    if (lane == 0) { sh1[w] = s; sh2[w] = ss; }
    __syncthreads();
    if (threadIdx.x == 0) {
        float S = 0.f, SS = 0.f;
        for (int i = 0; i < 8; i++) { S += sh1[i]; SS += sh2[i]; }
        float mean = S * (1.f / NPTS);
        float var  = (SS - (float)NPTS * mean * mean) * (1.f / (NPTS - 1));
        float sd   = sqrtf(fmaxf(var, 0.f));
        float scale = (f < 128) ? 0.3f : (f < 256) ? 0.18f : 0.1f;
        g_tau[f] = scale * (sd + 1e-6f) + 1e-4f;
    }
}

// ============================================================
// Stage 3: pairwise sigmoid ECDF + Bernstein partial sums
// grid: NFILT*4; block handles 512 x-values (2 per thread),
// full y (2048) pre-scaled by c = log2(e)/tau in shared.
// sigma(z) = 1/(1 + 2^((y-x)*c))  -> 2 MUFU + 3 FADD per pair
// ============================================================
__global__ void __launch_bounds__(256) pair_kernel() {
    int f    = blockIdx.x >> 2;
    int part = blockIdx.x & 3;
    const float* xp = g_x + f * NPTS + part * 512;
    const float* yp = g_y + f * NPTS;

    __shared__ float ys[NPTS];
    __shared__ float slu[512], sl1u[512];

    float c = 1.4426950408889634f / g_tau[f];
    int t = threadIdx.x;
    for (int j = t; j < NPTS; j += 256) ys[j] = yp[j] * c;
    __syncthreads();

    float x0 = xp[t] * c;
    float x1 = xp[t + 256] * c;
    float a0 = 0.f, b0 = 0.f, a1 = 0.f, b1 = 0.f;

    const float4* y4 = (const float4*)ys;
#pragma unroll 4
    for (int j = 0; j < NPTS / 4; j++) {
        float4 yv = y4[j];
        a0 += rcpf(1.f + ex2f(yv.x - x0));
        a1 += rcpf(1.f + ex2f(yv.x - x1));
        b0 += rcpf(1.f + ex2f(yv.y - x0));
        b1 += rcpf(1.f + ex2f(yv.y - x1));
        a0 += rcpf(1.f + ex2f(yv.z - x0));
        a1 += rcpf(1.f + ex2f(yv.z - x1));
        b0 += rcpf(1.f + ex2f(yv.w - x0));
        b1 += rcpf(1.f + ex2f(yv.w - x1));
    }

    float u0 = (a0 + b0) * (1.f / NPTS);
    float u1 = (a1 + b1) * (1.f / NPTS);
    u0 = fminf(fmaxf(u0, 1e-6f), 1.f - 1e-6f);
    u1 = fminf(fmaxf(u1, 1e-6f), 1.f - 1e-6f);

    slu[t]        = logf(u0);
    sl1u[t]       = logf(1.f - u0);
    slu[t + 256]  = logf(u1);
    sl1u[t + 256] = logf(1.f - u1);
    __syncthreads();

    if (t < NBINS) {
        float fn = (float)t, kn = (float)(KB - t);
        float logC = lgammaf((float)(KB + 1)) - lgammaf(fn + 1.f) - lgammaf(kn + 1.f);
        float acc = 0.f;
        for (int i = 0; i < 512; i++)
            acc += __expf(fmaf(fn, slu[i], fmaf(kn, sl1u[i], logC)));
        g_phat[(f * 4 + part) * NBINS + t] = acc;
    }
}

// ============================================================
// Stage 4: combine partials, f_js per bin, per-filter loss
// ============================================================
__global__ void __launch_bounds__(128) fjs_kernel() {
    int f = blockIdx.x;
    int n = threadIdx.x;
    float val = 0.f;
    if (n < NBINS) {
        float s = 0.f;
        for (int p = 0; p < 4; p++) s += g_phat[(f * 4 + p) * NBINS + n];
        float ph = s * (1.f / NPTS);
        float v  = fmaxf(ph * (float)NBINS, 1e-12f);
        float w  = 1.f / (1.f + v);
        float term = 0.5f * (1.f + v) *
            (0.6931471805599453f + logf(fmaxf(w, 1e-12f)) + log1pf(-w));
        val = term * (1.f / NBINS);
    }
    for (int o = 16; o > 0; o >>= 1) val += __shfl_down_sync(0xffffffffu, val, o);
    __shared__ float sh[4];
    int wi = threadIdx.x >> 5, lane = threadIdx.x & 31;
    if (lane == 0) sh[wi] = val;
    __syncthreads();
    if (threadIdx.x == 0) g_loss[f] = sh[0] + sh[1] + sh[2] + sh[3];
}

// ============================================================
// Stage 5: deterministic final reduction
// ============================================================
__global__ void __launch_bounds__(512) reduce_kernel(float* out) {
    int t = threadIdx.x;
    float v = (t < NFILT) ? g_loss[t] : 0.f;
    for (int o = 16; o > 0; o >>= 1) v += __shfl_down_sync(0xffffffffu, v, o);
    __shared__ float sh[16];
    if ((t & 31) == 0) sh[t >> 5] = v;
    __syncthreads();
    if (t == 0) {
        float s = 0.f;
        for (int i = 0; i < 16; i++) s += sh[i];
        out[0] = s * (1.f / 384.f);
    }
}

extern "C" void kernel_launch(void* const* d_in, const int* in_sizes, int n_in,
                              void* d_out, int out_size) {
    const float* Xg = (const float*)d_in[0];
    const float* Xd = (const float*)d_in[1];
    const float* W3 = (const float*)d_in[2];
    const float* W5 = (const float*)d_in[3];
    const float* W7 = (const float*)d_in[4];

    conv_kernel<<<1536, 256>>>(Xg, Xd, W3, W5, W7);
    tau_kernel<<<NFILT, 256>>>();
    pair_kernel<<<NFILT * 4, 256>>>();
    fjs_kernel<<<NFILT, 128>>>();
    reduce_kernel<<<1, 512>>>((float*)d_out);
}

// round 3
// speedup vs baseline: 1.2297x; 1.2297x over previous
#include <cuda_runtime.h>

#define NFILT 384      // 3 banks * 128 filters
#define NPTS  2048     // B*H'*W' = 2*32*32
#define KB    96
#define NBINS 97

// ---- scratch (static device globals; no allocation anywhere) ----
__device__ float g_x[NFILT * NPTS];
__device__ float g_y[NFILT * NPTS];
__device__ float g_tau[NFILT];
__device__ float g_phat[NFILT * 4 * NBINS];
__device__ float g_loss[NFILT];

__device__ __forceinline__ float ex2f(float x) {
    float r; asm("ex2.approx.f32 %0, %1;" : "=f"(r) : "f"(x)); return r;
}
__device__ __forceinline__ float rcpf(float x) {
    float r; asm("rcp.approx.f32 %0, %1;" : "=f"(r) : "f"(x)); return r;
}

// ============================================================
// Stage 1: direct conv, stride 2, zero padding, per-channel
// shared tile padded to 72x72 (pad 3 >= max k//2) -> no bounds
// checks in the tap loop.
// grid: 1536 = 3 banks * 2 srcs * 128 filters * 2 batches
// ============================================================
template <int KS>
__device__ __forceinline__ void conv_accum(const float* Xs, const float* Wc, float* acc) {
    const int P = KS / 2;
    int t = threadIdx.x;
#pragma unroll
    for (int r = 0; r < 4; r++) {
        int idx = t + r * 256;
        int oy = idx >> 5, ox = idx & 31;
        const float* xb = Xs + (2 * oy + 3 - P) * 72 + (2 * ox + 3 - P);
        float a = acc[r];
#pragma unroll
        for (int u = 0; u < KS; u++)
#pragma unroll
            for (int v = 0; v < KS; v++)
                a = fmaf(Wc[u * KS + v], xb[u * 72 + v], a);
        acc[r] = a;
    }
}

__global__ void __launch_bounds__(256) conv_kernel(
    const float* __restrict__ Xg, const float* __restrict__ Xd,
    const float* __restrict__ W3, const float* __restrict__ W5,
    const float* __restrict__ W7) {
    __shared__ float Xs[72 * 72];
    __shared__ float Ws[3 * 49];

    int bx   = blockIdx.x;
    int bank = bx >> 9;          // 0..2
    int rem  = bx & 511;
    int src  = rem >> 8;         // 0 = Xg, 1 = Xd
    int l    = (rem >> 1) & 127;
    int b    = rem & 1;

    const float* X = (src ? Xd : Xg) + b * 12288;
    const float* W;
    int KS;
    if (bank == 0)      { W = W3; KS = 3; }
    else if (bank == 1) { W = W5; KS = 5; }
    else                { W = W7; KS = 7; }
    int wsz = 3 * KS * KS;

    // zero borders once; interior rewritten per channel
    for (int i = threadIdx.x; i < 72 * 72; i += 256) Xs[i] = 0.f;
    for (int i = threadIdx.x; i < wsz; i += 256) Ws[i] = W[l * wsz + i];

    float acc[4] = {0.f, 0.f, 0.f, 0.f};
    for (int c = 0; c < 3; c++) {
        __syncthreads();
        for (int i = threadIdx.x; i < 4096; i += 256) {
            int r = i >> 6, col = i & 63;
            Xs[(r + 3) * 72 + (col + 3)] = X[c * 4096 + i];
        }
        __syncthreads();
        const float* Wc = Ws + c * KS * KS;
        if (bank == 0)      conv_accum<3>(Xs, Wc, acc);
        else if (bank == 1) conv_accum<5>(Xs, Wc, acc);
        else                conv_accum<7>(Xs, Wc, acc);
    }

    float* outp = (src ? g_y : g_x) + (bank * 128 + l) * NPTS + b * 1024;
#pragma unroll
    for (int r = 0; r < 4; r++) outp[threadIdx.x + r * 256] = acc[r];
}

// ============================================================
// Stage 2: per-filter tau = scale*(std(y, ddof=1)+1e-6)+1e-4
// ============================================================
__global__ void __launch_bounds__(256) tau_kernel() {
    int f = blockIdx.x;
    const float* y = g_y + f * NPTS;
    float s = 0.f, ss = 0.f;
    for (int i = threadIdx.x; i < NPTS; i += 256) {
        float v = y[i];
        s += v;
        ss = fmaf(v, v, ss);
    }
    __shared__ float sh1[8], sh2[8];
    for (int o = 16; o > 0; o >>= 1) {
        s  += __shfl_down_sync(0xffffffffu, s, o);
        ss += __shfl_down_sync(0xffffffffu, ss, o);
    }
    int w = threadIdx.x >> 5, lane = threadIdx.x & 31;
    if (lane == 0) { sh1[w] = s; sh2[w] = ss; }
    __syncthreads();
    if (threadIdx.x == 0) {
        float S = 0.f, SS = 0.f;
        for (int i = 0; i < 8; i++) { S += sh1[i]; SS += sh2[i]; }
        float mean = S * (1.f / NPTS);
        float var  = (SS - (float)NPTS * mean * mean) * (1.f / (NPTS - 1));
        float sd   = sqrtf(fmaxf(var, 0.f));
        float scale = (f < 128) ? 0.3f : (f < 256) ? 0.18f : 0.1f;
        g_tau[f] = scale * (sd + 1e-6f) + 1e-4f;
    }
}

// ============================================================
// Stage 3: pairwise sigmoid ECDF + Bernstein partial sums
// grid: NFILT*4; block handles 512 x-values (2 per thread),
// full y (2048) pre-scaled by c = log2(e)/tau in shared.
//
// sigma((x-y)/tau) = 1/(1 + 2^((y-x)*c)) = 1/t.
// Batched reciprocal over groups of 4 y-values:
//   sum_i 1/t_i = S/P  with  S <- S*t + P, P <- P*t  (exact algebra)
// => 1 ex2 + 1/4 rcp per pair instead of 1 ex2 + 1 rcp.
// Clamp ex2 arg at +30 so P <= ~2^120 stays finite (sigma error
// from the clamp < 2^-30, negligible).
// ============================================================
__global__ void __launch_bounds__(256) pair_kernel() {
    int f    = blockIdx.x >> 2;
    int part = blockIdx.x & 3;
    const float* xp = g_x + f * NPTS + part * 512;
    const float* yp = g_y + f * NPTS;

    __shared__ float ys[NPTS];
    __shared__ float slu[512], sl1u[512];

    float c = 1.4426950408889634f / g_tau[f];
    int t = threadIdx.x;
    for (int j = t; j < NPTS; j += 256) ys[j] = yp[j] * c;
    __syncthreads();

    float x0 = xp[t] * c;
    float x1 = xp[t + 256] * c;
    float acc0 = 0.f, acc1 = 0.f;

    const float4* y4 = (const float4*)ys;
#pragma unroll 2
    for (int j = 0; j < NPTS / 4; j++) {
        float4 yv = y4[j];
        // all 8 ex2 args first (independent MUFU chains)
        float e0x = ex2f(fminf(yv.x - x0, 30.f));
        float e0y = ex2f(fminf(yv.y - x0, 30.f));
        float e0z = ex2f(fminf(yv.z - x0, 30.f));
        float e0w = ex2f(fminf(yv.w - x0, 30.f));
        float e1x = ex2f(fminf(yv.x - x1, 30.f));
        float e1y = ex2f(fminf(yv.y - x1, 30.f));
        float e1z = ex2f(fminf(yv.z - x1, 30.f));
        float e1w = ex2f(fminf(yv.w - x1, 30.f));

        float t0, S0, P0, t1, S1, P1;
        t0 = 1.f + e0x; S0 = 1.f;              P0 = t0;
        t1 = 1.f + e1x; S1 = 1.f;              P1 = t1;
        t0 = 1.f + e0y; S0 = fmaf(S0, t0, P0); P0 *= t0;
        t1 = 1.f + e1y; S1 = fmaf(S1, t1, P1); P1 *= t1;
        t0 = 1.f + e0z; S0 = fmaf(S0, t0, P0); P0 *= t0;
        t1 = 1.f + e1z; S1 = fmaf(S1, t1, P1); P1 *= t1;
        t0 = 1.f + e0w; S0 = fmaf(S0, t0, P0); P0 *= t0;
        t1 = 1.f + e1w; S1 = fmaf(S1, t1, P1); P1 *= t1;

        acc0 = fmaf(S0, rcpf(P0), acc0);
        acc1 = fmaf(S1, rcpf(P1), acc1);
    }

    float u0 = acc0 * (1.f / NPTS);
    float u1 = acc1 * (1.f / NPTS);
    u0 = fminf(fmaxf(u0, 1e-6f), 1.f - 1e-6f);
    u1 = fminf(fmaxf(u1, 1e-6f), 1.f - 1e-6f);

    slu[t]        = logf(u0);
    sl1u[t]       = logf(1.f - u0);
    slu[t + 256]  = logf(u1);
    sl1u[t + 256] = logf(1.f - u1);
    __syncthreads();

    if (t < NBINS) {
        float fn = (float)t, kn = (float)(KB - t);
        float logC = lgammaf((float)(KB + 1)) - lgammaf(fn + 1.f) - lgammaf(kn + 1.f);
        float acc = 0.f;
        for (int i = 0; i < 512; i++)
            acc += __expf(fmaf(fn, slu[i], fmaf(kn, sl1u[i], logC)));
        g_phat[(f * 4 + part) * NBINS + t] = acc;
    }
}

// ============================================================
// Stage 4: combine partials, f_js per bin, per-filter loss
// ============================================================
__global__ void __launch_bounds__(128) fjs_kernel() {
    int f = blockIdx.x;
    int n = threadIdx.x;
    float val = 0.f;
    if (n < NBINS) {
        float s = 0.f;
        for (int p = 0; p < 4; p++) s += g_phat[(f * 4 + p) * NBINS + n];
        float ph = s * (1.f / NPTS);
        float v  = fmaxf(ph * (float)NBINS, 1e-12f);
        float w  = 1.f / (1.f + v);
        float term = 0.5f * (1.f + v) *
            (0.6931471805599453f + logf(fmaxf(w, 1e-12f)) + log1pf(-w));
        val = term * (1.f / NBINS);
    }
    for (int o = 16; o > 0; o >>= 1) val += __shfl_down_sync(0xffffffffu, val, o);
    __shared__ float sh[4];
    int wi = threadIdx.x >> 5, lane = threadIdx.x & 31;
    if (lane == 0) sh[wi] = val;
    __syncthreads();
    if (threadIdx.x == 0) g_loss[f] = sh[0] + sh[1] + sh[2] + sh[3];
}

// ============================================================
// Stage 5: deterministic final reduction
// ============================================================
__global__ void __launch_bounds__(512) reduce_kernel(float* out) {
    int t = threadIdx.x;
    float v = (t < NFILT) ? g_loss[t] : 0.f;
    for (int o = 16; o > 0; o >>= 1) v += __shfl_down_sync(0xffffffffu, v, o);
    __shared__ float sh[16];
    if ((t & 31) == 0) sh[t >> 5] = v;
    __syncthreads();
    if (t == 0) {
        float s = 0.f;
        for (int i = 0; i < 16; i++) s += sh[i];
        out[0] = s * (1.f / 384.f);
    }
}

extern "C" void kernel_launch(void* const* d_in, const int* in_sizes, int n_in,
                              void* d_out, int out_size) {
    const float* Xg = (const float*)d_in[0];
    const float* Xd = (const float*)d_in[1];
    const float* W3 = (const float*)d_in[2];
    const float* W5 = (const float*)d_in[3];
    const float* W7 = (const float*)d_in[4];

    conv_kernel<<<1536, 256>>>(Xg, Xd, W3, W5, W7);
    tau_kernel<<<NFILT, 256>>>();
    pair_kernel<<<NFILT * 4, 256>>>();
    fjs_kernel<<<NFILT, 128>>>();
    reduce_kernel<<<1, 512>>>((float*)d_out);
}

// round 4
// speedup vs baseline: 1.8767x; 1.5261x over previous
#include <cuda_runtime.h>

#define NFILT 384      // 3 banks * 128 filters
#define NPTS  2048     // B*H'*W' = 2*32*32
#define KB    96
#define NBINS 97

// ---- scratch (static device globals; no allocation anywhere) ----
__device__ float g_x[NFILT * NPTS];
__device__ float g_y[NFILT * NPTS];
__device__ float g_tau[NFILT];
__device__ float g_phat[NFILT * 4 * NBINS];
__device__ float g_loss[NFILT];

__device__ __forceinline__ float tanhf_approx(float x) {
    float r; asm("tanh.approx.f32 %0, %1;" : "=f"(r) : "f"(x)); return r;
}

// ============================================================
// Stage 1: direct conv, stride 2, zero padding, per-channel
// shared tile padded to 72x72 (pad 3 >= max k//2) -> no bounds
// checks in the tap loop.
// grid: 1536 = 3 banks * 2 srcs * 128 filters * 2 batches
// ============================================================
template <int KS>
__device__ __forceinline__ void conv_accum(const float* Xs, const float* Wc, float* acc) {
    const int P = KS / 2;
    int t = threadIdx.x;
#pragma unroll
    for (int r = 0; r < 4; r++) {
        int idx = t + r * 256;
        int oy = idx >> 5, ox = idx & 31;
        const float* xb = Xs + (2 * oy + 3 - P) * 72 + (2 * ox + 3 - P);
        float a = acc[r];
#pragma unroll
        for (int u = 0; u < KS; u++)
#pragma unroll
            for (int v = 0; v < KS; v++)
                a = fmaf(Wc[u * KS + v], xb[u * 72 + v], a);
        acc[r] = a;
    }
}

__global__ void __launch_bounds__(256) conv_kernel(
    const float* __restrict__ Xg, const float* __restrict__ Xd,
    const float* __restrict__ W3, const float* __restrict__ W5,
    const float* __restrict__ W7) {
    __shared__ float Xs[72 * 72];
    __shared__ float Ws[3 * 49];

    int bx   = blockIdx.x;
    int bank = bx >> 9;          // 0..2
    int rem  = bx & 511;
    int src  = rem >> 8;         // 0 = Xg, 1 = Xd
    int l    = (rem >> 1) & 127;
    int b    = rem & 1;

    const float* X = (src ? Xd : Xg) + b * 12288;
    const float* W;
    int KS;
    if (bank == 0)      { W = W3; KS = 3; }
    else if (bank == 1) { W = W5; KS = 5; }
    else                { W = W7; KS = 7; }
    int wsz = 3 * KS * KS;

    // zero borders once; interior rewritten per channel
    for (int i = threadIdx.x; i < 72 * 72; i += 256) Xs[i] = 0.f;
    for (int i = threadIdx.x; i < wsz; i += 256) Ws[i] = W[l * wsz + i];

    float acc[4] = {0.f, 0.f, 0.f, 0.f};
    for (int c = 0; c < 3; c++) {
        __syncthreads();
        for (int i = threadIdx.x; i < 4096; i += 256) {
            int r = i >> 6, col = i & 63;
            Xs[(r + 3) * 72 + (col + 3)] = X[c * 4096 + i];
        }
        __syncthreads();
        const float* Wc = Ws + c * KS * KS;
        if (bank == 0)      conv_accum<3>(Xs, Wc, acc);
        else if (bank == 1) conv_accum<5>(Xs, Wc, acc);
        else                conv_accum<7>(Xs, Wc, acc);
    }

    float* outp = (src ? g_y : g_x) + (bank * 128 + l) * NPTS + b * 1024;
#pragma unroll
    for (int r = 0; r < 4; r++) outp[threadIdx.x + r * 256] = acc[r];
}

// ============================================================
// Stage 2: per-filter tau = scale*(std(y, ddof=1)+1e-6)+1e-4
// ============================================================
__global__ void __launch_bounds__(256) tau_kernel() {
    int f = blockIdx.x;
    const float* y = g_y + f * NPTS;
    float s = 0.f, ss = 0.f;
    for (int i = threadIdx.x; i < NPTS; i += 256) {
        float v = y[i];
        s += v;
        ss = fmaf(v, v, ss);
    }
    __shared__ float sh1[8], sh2[8];
    for (int o = 16; o > 0; o >>= 1) {
        s  += __shfl_down_sync(0xffffffffu, s, o);
        ss += __shfl_down_sync(0xffffffffu, ss, o);
    }
    int w = threadIdx.x >> 5, lane = threadIdx.x & 31;
    if (lane == 0) { sh1[w] = s; sh2[w] = ss; }
    __syncthreads();
    if (threadIdx.x == 0) {
        float S = 0.f, SS = 0.f;
        for (int i = 0; i < 8; i++) { S += sh1[i]; SS += sh2[i]; }
        float mean = S * (1.f / NPTS);
        float var  = (SS - (float)NPTS * mean * mean) * (1.f / (NPTS - 1));
        float sd   = sqrtf(fmaxf(var, 0.f));
        float scale = (f < 128) ? 0.3f : (f < 256) ? 0.18f : 0.1f;
        g_tau[f] = scale * (sd + 1e-6f) + 1e-4f;
    }
}

// ============================================================
// Stage 3: pairwise ECDF via tanh + Bernstein partial sums
// sigma((x-y)/tau) = 0.5 + 0.5*tanh((x-y)/(2*tau))
// => U_i = 0.5 + (0.5/N) * sum_j tanh(x'_i + yneg'_j)
// with x' = x/(2 tau), yneg' = -y/(2 tau).
// Per pair: FADD + MUFU.TANH + FADD  (1 MUFU, 2 FMA-pipe).
// grid: NFILT*4; block handles 512 x (2 per thread), full y in smem.
// ============================================================
__global__ void __launch_bounds__(256) pair_kernel() {
    int f    = blockIdx.x >> 2;
    int part = blockIdx.x & 3;
    const float* xp = g_x + f * NPTS + part * 512;
    const float* yp = g_y + f * NPTS;

    __shared__ float ys[NPTS];     // holds -y / (2 tau)
    __shared__ float slu[512], sl1u[512];

    float c2 = 0.5f / g_tau[f];
    int t = threadIdx.x;
    for (int j = t; j < NPTS; j += 256) ys[j] = yp[j] * (-c2);
    __syncthreads();

    float x0 = xp[t] * c2;
    float x1 = xp[t + 256] * c2;
    float a0 = 0.f, b0 = 0.f, a1 = 0.f, b1 = 0.f;

    const float4* y4 = (const float4*)ys;
#pragma unroll 4
    for (int j = 0; j < NPTS / 4; j++) {
        float4 yv = y4[j];
        a0 += tanhf_approx(yv.x + x0);
        a1 += tanhf_approx(yv.x + x1);
        b0 += tanhf_approx(yv.y + x0);
        b1 += tanhf_approx(yv.y + x1);
        a0 += tanhf_approx(yv.z + x0);
        a1 += tanhf_approx(yv.z + x1);
        b0 += tanhf_approx(yv.w + x0);
        b1 += tanhf_approx(yv.w + x1);
    }

    float u0 = fmaf(a0 + b0, 0.5f / NPTS, 0.5f);
    float u1 = fmaf(a1 + b1, 0.5f / NPTS, 0.5f);
    u0 = fminf(fmaxf(u0, 1e-6f), 1.f - 1e-6f);
    u1 = fminf(fmaxf(u1, 1e-6f), 1.f - 1e-6f);

    slu[t]        = logf(u0);
    sl1u[t]       = logf(1.f - u0);
    slu[t + 256]  = logf(u1);
    sl1u[t + 256] = logf(1.f - u1);
    __syncthreads();

    if (t < NBINS) {
        float fn = (float)t, kn = (float)(KB - t);
        float logC = lgammaf((float)(KB + 1)) - lgammaf(fn + 1.f) - lgammaf(kn + 1.f);
        float acc = 0.f;
        for (int i = 0; i < 512; i++)
            acc += __expf(fmaf(fn, slu[i], fmaf(kn, sl1u[i], logC)));
        g_phat[(f * 4 + part) * NBINS + t] = acc;
    }
}

// ============================================================
// Stage 4: combine partials, f_js per bin, per-filter loss
// ============================================================
__global__ void __launch_bounds__(128) fjs_kernel() {
    int f = blockIdx.x;
    int n = threadIdx.x;
    float val = 0.f;
    if (n < NBINS) {
        float s = 0.f;
        for (int p = 0; p < 4; p++) s += g_phat[(f * 4 + p) * NBINS + n];
        float ph = s * (1.f / NPTS);
        float v  = fmaxf(ph * (float)NBINS, 1e-12f);
        float w  = 1.f / (1.f + v);
        float term = 0.5f * (1.f + v) *
            (0.6931471805599453f + logf(fmaxf(w, 1e-12f)) + log1pf(-w));
        val = term * (1.f / NBINS);
    }
    for (int o = 16; o > 0; o >>= 1) val += __shfl_down_sync(0xffffffffu, val, o);
    __shared__ float sh[4];
    int wi = threadIdx.x >> 5, lane = threadIdx.x & 31;
    if (lane == 0) sh[wi] = val;
    __syncthreads();
    if (threadIdx.x == 0) g_loss[f] = sh[0] + sh[1] + sh[2] + sh[3];
}

// ============================================================
// Stage 5: deterministic final reduction
// ============================================================
__global__ void __launch_bounds__(512) reduce_kernel(float* out) {
    int t = threadIdx.x;
    float v = (t < NFILT) ? g_loss[t] : 0.f;
    for (int o = 16; o > 0; o >>= 1) v += __shfl_down_sync(0xffffffffu, v, o);
    __shared__ float sh[16];
    if ((t & 31) == 0) sh[t >> 5] = v;
    __syncthreads();
    if (t == 0) {
        float s = 0.f;
        for (int i = 0; i < 16; i++) s += sh[i];
        out[0] = s * (1.f / 384.f);
    }
}

extern "C" void kernel_launch(void* const* d_in, const int* in_sizes, int n_in,
                              void* d_out, int out_size) {
    const float* Xg = (const float*)d_in[0];
    const float* Xd = (const float*)d_in[1];
    const float* W3 = (const float*)d_in[2];
    const float* W5 = (const float*)d_in[3];
    const float* W7 = (const float*)d_in[4];

    conv_kernel<<<1536, 256>>>(Xg, Xd, W3, W5, W7);
    tau_kernel<<<NFILT, 256>>>();
    pair_kernel<<<NFILT * 4, 256>>>();
    fjs_kernel<<<NFILT, 128>>>();
    reduce_kernel<<<1, 512>>>((float*)d_out);
}

// round 5
// speedup vs baseline: 1.8831x; 1.0034x over previous
#include <cuda_runtime.h>
#include <cuda_fp16.h>

#define NFILT 384      // 3 banks * 128 filters
#define NPTS  2048     // B*H'*W' = 2*32*32
#define KB    96
#define NBINS 97

// ---- scratch (static device globals; no allocation anywhere) ----
__device__ float g_x[NFILT * NPTS];
__device__ float g_y[NFILT * NPTS];
__device__ float g_tau[NFILT];
__device__ float g_phat[NFILT * 4 * NBINS];
__device__ float g_loss[NFILT];

__device__ __forceinline__ unsigned tanh2u(unsigned x) {
    unsigned r; asm("tanh.approx.f16x2 %0, %1;" : "=r"(r) : "r"(x)); return r;
}

// ============================================================
// Stage 1: direct conv, stride 2, zero padding, per-channel
// shared tile padded to 72x72 (pad 3 >= max k//2) -> no bounds
// checks in the tap loop.
// grid: 1536 = 3 banks * 2 srcs * 128 filters * 2 batches
// ============================================================
template <int KS>
__device__ __forceinline__ void conv_accum(const float* Xs, const float* Wc, float* acc) {
    const int P = KS / 2;
    int t = threadIdx.x;
#pragma unroll
    for (int r = 0; r < 4; r++) {
        int idx = t + r * 256;
        int oy = idx >> 5, ox = idx & 31;
        const float* xb = Xs + (2 * oy + 3 - P) * 72 + (2 * ox + 3 - P);
        float a = acc[r];
#pragma unroll
        for (int u = 0; u < KS; u++)
#pragma unroll
            for (int v = 0; v < KS; v++)
                a = fmaf(Wc[u * KS + v], xb[u * 72 + v], a);
        acc[r] = a;
    }
}

__global__ void __launch_bounds__(256) conv_kernel(
    const float* __restrict__ Xg, const float* __restrict__ Xd,
    const float* __restrict__ W3, const float* __restrict__ W5,
    const float* __restrict__ W7) {
    __shared__ float Xs[72 * 72];
    __shared__ float Ws[3 * 49];

    int bx   = blockIdx.x;
    int bank = bx >> 9;          // 0..2
    int rem  = bx & 511;
    int src  = rem >> 8;         // 0 = Xg, 1 = Xd
    int l    = (rem >> 1) & 127;
    int b    = rem & 1;

    const float* X = (src ? Xd : Xg) + b * 12288;
    const float* W;
    int KS;
    if (bank == 0)      { W = W3; KS = 3; }
    else if (bank == 1) { W = W5; KS = 5; }
    else                { W = W7; KS = 7; }
    int wsz = 3 * KS * KS;

    // zero borders once; interior rewritten per channel
    for (int i = threadIdx.x; i < 72 * 72; i += 256) Xs[i] = 0.f;
    for (int i = threadIdx.x; i < wsz; i += 256) Ws[i] = W[l * wsz + i];

    float acc[4] = {0.f, 0.f, 0.f, 0.f};
    for (int c = 0; c < 3; c++) {
        __syncthreads();
        for (int i = threadIdx.x; i < 4096; i += 256) {
            int r = i >> 6, col = i & 63;
            Xs[(r + 3) * 72 + (col + 3)] = X[c * 4096 + i];
        }
        __syncthreads();
        const float* Wc = Ws + c * KS * KS;
        if (bank == 0)      conv_accum<3>(Xs, Wc, acc);
        else if (bank == 1) conv_accum<5>(Xs, Wc, acc);
        else                conv_accum<7>(Xs, Wc, acc);
    }

    float* outp = (src ? g_y : g_x) + (bank * 128 + l) * NPTS + b * 1024;
#pragma unroll
    for (int r = 0; r < 4; r++) outp[threadIdx.x + r * 256] = acc[r];
}

// ============================================================
// Stage 2: per-filter tau = scale*(std(y, ddof=1)+1e-6)+1e-4
// ============================================================
__global__ void __launch_bounds__(256) tau_kernel() {
    int f = blockIdx.x;
    const float* y = g_y + f * NPTS;
    float s = 0.f, ss = 0.f;
    for (int i = threadIdx.x; i < NPTS; i += 256) {
        float v = y[i];
        s += v;
        ss = fmaf(v, v, ss);
    }
    __shared__ float sh1[8], sh2[8];
    for (int o = 16; o > 0; o >>= 1) {
        s  += __shfl_down_sync(0xffffffffu, s, o);
        ss += __shfl_down_sync(0xffffffffu, ss, o);
    }
    int w = threadIdx.x >> 5, lane = threadIdx.x & 31;
    if (lane == 0) { sh1[w] = s; sh2[w] = ss; }
    __syncthreads();
    if (threadIdx.x == 0) {
        float S = 0.f, SS = 0.f;
        for (int i = 0; i < 8; i++) { S += sh1[i]; SS += sh2[i]; }
        float mean = S * (1.f / NPTS);
        float var  = (SS - (float)NPTS * mean * mean) * (1.f / (NPTS - 1));
        float sd   = sqrtf(fmaxf(var, 0.f));
        float scale = (f < 128) ? 0.3f : (f < 256) ? 0.18f : 0.1f;
        g_tau[f] = scale * (sd + 1e-6f) + 1e-4f;
    }
}

// ============================================================
// Stage 3: pairwise ECDF via tanh.approx.f16x2
// sigma((x-y)/tau) = 0.5 + 0.5*tanh((x-y)/(2 tau))
// y pre-scaled by -1/(2 tau) and packed to f16x2 in smem.
// Per pair: 0.5 HADD2 + 0.5 MUFU.TANH.f16x2 + 1 cvt + 1 FADD(f32 acc)
// -> MUFU-bound at 0.5 MUFU/pair (2x R4's rate).
// grid: NFILT*4; block handles 512 x (2 per thread).
// ============================================================
__global__ void __launch_bounds__(256) pair_kernel() {
    int f    = blockIdx.x >> 2;
    int part = blockIdx.x & 3;
    const float* xp = g_x + f * NPTS + part * 512;
    const float* yp = g_y + f * NPTS;

    __shared__ __half2 ys2[NPTS / 2];   // -y / (2 tau), packed
    __shared__ float slu[512], sl1u[512];

    float c2 = 0.5f / g_tau[f];
    int t = threadIdx.x;
    for (int j = t; j < NPTS / 2; j += 256) {
        float ya = yp[2 * j]     * (-c2);
        float yb = yp[2 * j + 1] * (-c2);
        ys2[j] = __floats2half2_rn(ya, yb);
    }
    __syncthreads();

    __half2 x0h = __float2half2_rn(xp[t] * c2);
    __half2 x1h = __float2half2_rn(xp[t + 256] * c2);
    float a0 = 0.f, b0 = 0.f, a1 = 0.f, b1 = 0.f;

    const uint4* y8 = (const uint4*)ys2;   // 4 half2 per uint4 (8 y)
#pragma unroll 2
    for (int j = 0; j < NPTS / 8; j++) {
        uint4 v = y8[j];
#pragma unroll
        for (int q = 0; q < 4; q++) {
            unsigned raw = (q == 0) ? v.x : (q == 1) ? v.y : (q == 2) ? v.z : v.w;
            __half2 yv = *reinterpret_cast<__half2*>(&raw);

            __half2 s0 = __hadd2(yv, x0h);
            __half2 s1 = __hadd2(yv, x1h);
            unsigned r0 = tanh2u(*reinterpret_cast<unsigned*>(&s0));
            unsigned r1 = tanh2u(*reinterpret_cast<unsigned*>(&s1));
            float2 f0 = __half22float2(*reinterpret_cast<__half2*>(&r0));
            float2 f1 = __half22float2(*reinterpret_cast<__half2*>(&r1));
            a0 += f0.x; b0 += f0.y;
            a1 += f1.x; b1 += f1.y;
        }
    }

    float u0 = fmaf(a0 + b0, 0.5f / NPTS, 0.5f);
    float u1 = fmaf(a1 + b1, 0.5f / NPTS, 0.5f);
    u0 = fminf(fmaxf(u0, 1e-6f), 1.f - 1e-6f);
    u1 = fminf(fmaxf(u1, 1e-6f), 1.f - 1e-6f);

    slu[t]        = logf(u0);
    sl1u[t]       = logf(1.f - u0);
    slu[t + 256]  = logf(u1);
    sl1u[t + 256] = logf(1.f - u1);
    __syncthreads();

    if (t < NBINS) {
        float fn = (float)t, kn = (float)(KB - t);
        float logC = lgammaf((float)(KB + 1)) - lgammaf(fn + 1.f) - lgammaf(kn + 1.f);
        float acc = 0.f;
        for (int i = 0; i < 512; i++)
            acc += __expf(fmaf(fn, slu[i], fmaf(kn, sl1u[i], logC)));
        g_phat[(f * 4 + part) * NBINS + t] = acc;
    }
}

// ============================================================
// Stage 4: combine partials, f_js per bin, per-filter loss
// ============================================================
__global__ void __launch_bounds__(128) fjs_kernel() {
    int f = blockIdx.x;
    int n = threadIdx.x;
    float val = 0.f;
    if (n < NBINS) {
        float s = 0.f;
        for (int p = 0; p < 4; p++) s += g_phat[(f * 4 + p) * NBINS + n];
        float ph = s * (1.f / NPTS);
        float v  = fmaxf(ph * (float)NBINS, 1e-12f);
        float w  = 1.f / (1.f + v);
        float term = 0.5f * (1.f + v) *
            (0.6931471805599453f + logf(fmaxf(w, 1e-12f)) + log1pf(-w));
        val = term * (1.f / NBINS);
    }
    for (int o = 16; o > 0; o >>= 1) val += __shfl_down_sync(0xffffffffu, val, o);
    __shared__ float sh[4];
    int wi = threadIdx.x >> 5, lane = threadIdx.x & 31;
    if (lane == 0) sh[wi] = val;
    __syncthreads();
    if (threadIdx.x == 0) g_loss[f] = sh[0] + sh[1] + sh[2] + sh[3];
}

// ============================================================
// Stage 5: deterministic final reduction
// ============================================================
__global__ void __launch_bounds__(512) reduce_kernel(float* out) {
    int t = threadIdx.x;
    float v = (t < NFILT) ? g_loss[t] : 0.f;
    for (int o = 16; o > 0; o >>= 1) v += __shfl_down_sync(0xffffffffu, v, o);
    __shared__ float sh[16];
    if ((t & 31) == 0) sh[t >> 5] = v;
    __syncthreads();
    if (t == 0) {
        float s = 0.f;
        for (int i = 0; i < 16; i++) s += sh[i];
        out[0] = s * (1.f / 384.f);
    }
}

extern "C" void kernel_launch(void* const* d_in, const int* in_sizes, int n_in,
                              void* d_out, int out_size) {
    const float* Xg = (const float*)d_in[0];
    const float* Xd = (const float*)d_in[1];
    const float* W3 = (const float*)d_in[2];
    const float* W5 = (const float*)d_in[3];
    const float* W7 = (const float*)d_in[4];

    conv_kernel<<<1536, 256>>>(Xg, Xd, W3, W5, W7);
    tau_kernel<<<NFILT, 256>>>();
    pair_kernel<<<NFILT * 4, 256>>>();
    fjs_kernel<<<NFILT, 128>>>();
    reduce_kernel<<<1, 512>>>((float*)d_out);
}

// round 6
// speedup vs baseline: 6.4472x; 3.4238x over previous
#include <cuda_runtime.h>

#define NFILT 384      // 3 banks * 128 filters
#define NPTS  2048     // B*H'*W' = 2*32*32
#define KB    96
#define NBINS 97
#define NHB   256      // histogram bins for y compression

// ---- scratch (static device globals; no allocation anywhere) ----
__device__ float g_x[NFILT * NPTS];
__device__ float g_y[NFILT * NPTS];
__device__ float g_tau[NFILT];
__device__ float g_hw[NFILT * NHB];   // bin weights (counts)
__device__ float g_hc[NFILT * NHB];   // bin centroids (raw y units)
__device__ float g_phat[NFILT * 4 * NBINS];
__device__ float g_loss[NFILT];

__device__ __forceinline__ float tanhf_approx(float x) {
    float r; asm("tanh.approx.f32 %0, %1;" : "=f"(r) : "f"(x)); return r;
}

// ============================================================
// Stage 1: direct conv, stride 2, zero padding, per-channel
// shared tile padded to 72x72 -> no bounds checks in tap loop.
// grid: 1536 = 3 banks * 2 srcs * 128 filters * 2 batches
// ============================================================
template <int KS>
__device__ __forceinline__ void conv_accum(const float* Xs, const float* Wc, float* acc) {
    const int P = KS / 2;
    int t = threadIdx.x;
#pragma unroll
    for (int r = 0; r < 4; r++) {
        int idx = t + r * 256;
        int oy = idx >> 5, ox = idx & 31;
        const float* xb = Xs + (2 * oy + 3 - P) * 72 + (2 * ox + 3 - P);
        float a = acc[r];
#pragma unroll
        for (int u = 0; u < KS; u++)
#pragma unroll
            for (int v = 0; v < KS; v++)
                a = fmaf(Wc[u * KS + v], xb[u * 72 + v], a);
        acc[r] = a;
    }
}

__global__ void __launch_bounds__(256) conv_kernel(
    const float* __restrict__ Xg, const float* __restrict__ Xd,
    const float* __restrict__ W3, const float* __restrict__ W5,
    const float* __restrict__ W7) {
    __shared__ float Xs[72 * 72];
    __shared__ float Ws[3 * 49];

    int bx   = blockIdx.x;
    int bank = bx >> 9;
    int rem  = bx & 511;
    int src  = rem >> 8;
    int l    = (rem >> 1) & 127;
    int b    = rem & 1;

    const float* X = (src ? Xd : Xg) + b * 12288;
    const float* W;
    int KS;
    if (bank == 0)      { W = W3; KS = 3; }
    else if (bank == 1) { W = W5; KS = 5; }
    else                { W = W7; KS = 7; }
    int wsz = 3 * KS * KS;

    for (int i = threadIdx.x; i < 72 * 72; i += 256) Xs[i] = 0.f;
    for (int i = threadIdx.x; i < wsz; i += 256) Ws[i] = W[l * wsz + i];

    float acc[4] = {0.f, 0.f, 0.f, 0.f};
    for (int c = 0; c < 3; c++) {
        __syncthreads();
        for (int i = threadIdx.x; i < 4096; i += 256) {
            int r = i >> 6, col = i & 63;
            Xs[(r + 3) * 72 + (col + 3)] = X[c * 4096 + i];
        }
        __syncthreads();
        const float* Wc = Ws + c * KS * KS;
        if (bank == 0)      conv_accum<3>(Xs, Wc, acc);
        else if (bank == 1) conv_accum<5>(Xs, Wc, acc);
        else                conv_accum<7>(Xs, Wc, acc);
    }

    float* outp = (src ? g_y : g_x) + (bank * 128 + l) * NPTS + b * 1024;
#pragma unroll
    for (int r = 0; r < 4; r++) outp[threadIdx.x + r * 256] = acc[r];
}

// ============================================================
// Stage 2: per-filter tau = scale*(std(y, ddof=1)+1e-6)+1e-4
// ============================================================
__global__ void __launch_bounds__(256) tau_kernel() {
    int f = blockIdx.x;
    const float* y = g_y + f * NPTS;
    float s = 0.f, ss = 0.f;
    for (int i = threadIdx.x; i < NPTS; i += 256) {
        float v = y[i];
        s += v;
        ss = fmaf(v, v, ss);
    }
    __shared__ float sh1[8], sh2[8];
    for (int o = 16; o > 0; o >>= 1) {
        s  += __shfl_down_sync(0xffffffffu, s, o);
        ss += __shfl_down_sync(0xffffffffu, ss, o);
    }
    int w = threadIdx.x >> 5, lane = threadIdx.x & 31;
    if (lane == 0) { sh1[w] = s; sh2[w] = ss; }
    __syncthreads();
    if (threadIdx.x == 0) {
        float S = 0.f, SS = 0.f;
        for (int i = 0; i < 8; i++) { S += sh1[i]; SS += sh2[i]; }
        float mean = S * (1.f / NPTS);
        float var  = (SS - (float)NPTS * mean * mean) * (1.f / (NPTS - 1));
        float sd   = sqrtf(fmaxf(var, 0.f));
        float scale = (f < 128) ? 0.3f : (f < 256) ? 0.18f : 0.1f;
        g_tau[f] = scale * (sd + 1e-6f) + 1e-4f;
    }
}

// ============================================================
// Stage 2b: per-filter y histogram with centroids.
// Deterministic: integer atomics only (int counts + fixed-point
// ull sums, scale 2^12 -> centroid quantization ~range/2^21).
// ============================================================
__global__ void __launch_bounds__(256) hist_kernel() {
    int f = blockIdx.x;
    const float* y = g_y + f * NPTS;

    __shared__ float ys[NPTS];
    __shared__ int   cnt[NHB];
    __shared__ unsigned long long sq[NHB];
    __shared__ float rmin[8], rmax[8];

    int t = threadIdx.x;
    for (int i = t; i < NHB; i += 256) { cnt[i] = 0; sq[i] = 0ull; }

    float lmin = 1e30f, lmax = -1e30f;
    for (int i = t; i < NPTS; i += 256) {
        float v = y[i];
        ys[i] = v;
        lmin = fminf(lmin, v);
        lmax = fmaxf(lmax, v);
    }
    for (int o = 16; o > 0; o >>= 1) {
        lmin = fminf(lmin, __shfl_down_sync(0xffffffffu, lmin, o));
        lmax = fmaxf(lmax, __shfl_down_sync(0xffffffffu, lmax, o));
    }
    int w = t >> 5, lane = t & 31;
    if (lane == 0) { rmin[w] = lmin; rmax[w] = lmax; }
    __syncthreads();

    float bmin = rmin[0], bmax = rmax[0];
#pragma unroll
    for (int i = 1; i < 8; i++) {
        bmin = fminf(bmin, rmin[i]);
        bmax = fmaxf(bmax, rmax[i]);
    }
    float scale = (float)NHB / ((bmax - bmin) * (1.f + 1e-6f) + 1e-20f);

    for (int i = t; i < NPTS; i += 256) {
        float q = (ys[i] - bmin) * scale;            // [0, NHB)
        int b = min((int)q, NHB - 1);
        atomicAdd(&cnt[b], 1);
        atomicAdd(&sq[b], (unsigned long long)(q * 4096.0f + 0.5f));
    }
    __syncthreads();

    for (int b = t; b < NHB; b += 256) {
        int c = cnt[b];
        float cen = bmin;
        if (c > 0)
            cen = bmin + ((float)sq[b] / (4096.0f * (float)c)) / scale;
        g_hw[f * NHB + b] = (float)c;
        g_hc[f * NHB + b] = cen;
    }
}

// ============================================================
// Stage 3: ECDF via weighted tanh over histogram bins
// sigma((x-y)/tau) = 0.5 + 0.5*tanh((x-y)/(2 tau))
// U_i = 0.5 + (0.5/N) * sum_b w_b * tanh(c2*x_i - c2*c_b)
// grid: NFILT*4; block handles 512 x (2 per thread), 256 bins.
// ============================================================
__global__ void __launch_bounds__(256) pair_kernel() {
    int f    = blockIdx.x >> 2;
    int part = blockIdx.x & 3;
    const float* xp = g_x + f * NPTS + part * 512;

    __shared__ float2 hb[NHB];      // (-c2*centroid, weight)
    __shared__ float slu[512], sl1u[512];

    float c2 = 0.5f / g_tau[f];
    int t = threadIdx.x;
    for (int i = t; i < NHB; i += 256)
        hb[i] = make_float2(-c2 * g_hc[f * NHB + i], g_hw[f * NHB + i]);
    __syncthreads();

    float x0 = xp[t] * c2;
    float x1 = xp[t + 256] * c2;
    float a0 = 0.f, b0 = 0.f, a1 = 0.f, b1 = 0.f;

#pragma unroll 4
    for (int b = 0; b < NHB; b += 2) {
        float2 h0 = hb[b];
        float2 h1 = hb[b + 1];
        a0 = fmaf(h0.y, tanhf_approx(h0.x + x0), a0);
        a1 = fmaf(h0.y, tanhf_approx(h0.x + x1), a1);
        b0 = fmaf(h1.y, tanhf_approx(h1.x + x0), b0);
        b1 = fmaf(h1.y, tanhf_approx(h1.x + x1), b1);
    }

    float u0 = fmaf(a0 + b0, 0.5f / NPTS, 0.5f);
    float u1 = fmaf(a1 + b1, 0.5f / NPTS, 0.5f);
    u0 = fminf(fmaxf(u0, 1e-6f), 1.f - 1e-6f);
    u1 = fminf(fmaxf(u1, 1e-6f), 1.f - 1e-6f);

    slu[t]        = logf(u0);
    sl1u[t]       = logf(1.f - u0);
    slu[t + 256]  = logf(u1);
    sl1u[t + 256] = logf(1.f - u1);
    __syncthreads();

    if (t < NBINS) {
        float fn = (float)t, kn = (float)(KB - t);
        float logC = lgammaf((float)(KB + 1)) - lgammaf(fn + 1.f) - lgammaf(kn + 1.f);
        float acc = 0.f;
        for (int i = 0; i < 512; i++)
            acc += __expf(fmaf(fn, slu[i], fmaf(kn, sl1u[i], logC)));
        g_phat[(f * 4 + part) * NBINS + t] = acc;
    }
}

// ============================================================
// Stage 4: combine partials, f_js per bin, per-filter loss
// ============================================================
__global__ void __launch_bounds__(128) fjs_kernel() {
    int f = blockIdx.x;
    int n = threadIdx.x;
    float val = 0.f;
    if (n < NBINS) {
        float s = 0.f;
        for (int p = 0; p < 4; p++) s += g_phat[(f * 4 + p) * NBINS + n];
        float ph = s * (1.f / NPTS);
        float v  = fmaxf(ph * (float)NBINS, 1e-12f);
        float w  = 1.f / (1.f + v);
        float term = 0.5f * (1.f + v) *
            (0.6931471805599453f + logf(fmaxf(w, 1e-12f)) + log1pf(-w));
        val = term * (1.f / NBINS);
    }
    for (int o = 16; o > 0; o >>= 1) val += __shfl_down_sync(0xffffffffu, val, o);
    __shared__ float sh[4];
    int wi = threadIdx.x >> 5, lane = threadIdx.x & 31;
    if (lane == 0) sh[wi] = val;
    __syncthreads();
    if (threadIdx.x == 0) g_loss[f] = sh[0] + sh[1] + sh[2] + sh[3];
}

// ============================================================
// Stage 5: deterministic final reduction
// ============================================================
__global__ void __launch_bounds__(512) reduce_kernel(float* out) {
    int t = threadIdx.x;
    float v = (t < NFILT) ? g_loss[t] : 0.f;
    for (int o = 16; o > 0; o >>= 1) v += __shfl_down_sync(0xffffffffu, v, o);
    __shared__ float sh[16];
    if ((t & 31) == 0) sh[t >> 5] = v;
    __syncthreads();
    if (t == 0) {
        float s = 0.f;
        for (int i = 0; i < 16; i++) s += sh[i];
        out[0] = s * (1.f / 384.f);
    }
}

extern "C" void kernel_launch(void* const* d_in, const int* in_sizes, int n_in,
                              void* d_out, int out_size) {
    const float* Xg = (const float*)d_in[0];
    const float* Xd = (const float*)d_in[1];
    const float* W3 = (const float*)d_in[2];
    const float* W5 = (const float*)d_in[3];
    const float* W7 = (const float*)d_in[4];

    conv_kernel<<<1536, 256>>>(Xg, Xd, W3, W5, W7);
    tau_kernel<<<NFILT, 256>>>();
    hist_kernel<<<NFILT, 256>>>();
    pair_kernel<<<NFILT * 4, 256>>>();
    fjs_kernel<<<NFILT, 128>>>();
    reduce_kernel<<<1, 512>>>((float*)d_out);
}

// round 7
// speedup vs baseline: 9.3118x; 1.4443x over previous
#include <cuda_runtime.h>

#define NFILT 384      // 3 banks * 128 filters
#define NPTS  2048     // B*H'*W' = 2*32*32
#define KB    96
#define NBINS 97
#define NHB   64       // y-histogram bins (ECDF compression)
#define NUB   512      // u-histogram bins (Bernstein compression)

// ---- scratch (static device globals; no allocation anywhere) ----
__device__ float g_x[NFILT * NPTS];
__device__ float g_y[NFILT * NPTS];
__device__ float g_loss[NFILT];

__device__ __forceinline__ float tanhf_approx(float x) {
    float r; asm("tanh.approx.f32 %0, %1;" : "=f"(r) : "f"(x)); return r;
}

// ============================================================
// Stage 1: direct conv, stride 2, zero padding, per-channel
// shared tile padded to 72x72 -> no bounds checks in tap loop.
// grid: 1536 = 3 banks * 2 srcs * 128 filters * 2 batches
// ============================================================
template <int KS>
__device__ __forceinline__ void conv_accum(const float* Xs, const float* Wc, float* acc) {
    const int P = KS / 2;
    int t = threadIdx.x;
#pragma unroll
    for (int r = 0; r < 4; r++) {
        int idx = t + r * 256;
        int oy = idx >> 5, ox = idx & 31;
        const float* xb = Xs + (2 * oy + 3 - P) * 72 + (2 * ox + 3 - P);
        float a = acc[r];
#pragma unroll
        for (int u = 0; u < KS; u++)
#pragma unroll
            for (int v = 0; v < KS; v++)
                a = fmaf(Wc[u * KS + v], xb[u * 72 + v], a);
        acc[r] = a;
    }
}

__global__ void __launch_bounds__(256) conv_kernel(
    const float* __restrict__ Xg, const float* __restrict__ Xd,
    const float* __restrict__ W3, const float* __restrict__ W5,
    const float* __restrict__ W7) {
    __shared__ float Xs[72 * 72];
    __shared__ float Ws[3 * 49];

    int bx   = blockIdx.x;
    int bank = bx >> 9;
    int rem  = bx & 511;
    int src  = rem >> 8;
    int l    = (rem >> 1) & 127;
    int b    = rem & 1;

    const float* X = (src ? Xd : Xg) + b * 12288;
    const float* W;
    int KS;
    if (bank == 0)      { W = W3; KS = 3; }
    else if (bank == 1) { W = W5; KS = 5; }
    else                { W = W7; KS = 7; }
    int wsz = 3 * KS * KS;

    for (int i = threadIdx.x; i < 72 * 72; i += 256) Xs[i] = 0.f;
    for (int i = threadIdx.x; i < wsz; i += 256) Ws[i] = W[l * wsz + i];

    float acc[4] = {0.f, 0.f, 0.f, 0.f};
    for (int c = 0; c < 3; c++) {
        __syncthreads();
        for (int i = threadIdx.x; i < 4096; i += 256) {
            int r = i >> 6, col = i & 63;
            Xs[(r + 3) * 72 + (col + 3)] = X[c * 4096 + i];
        }
        __syncthreads();
        const float* Wc = Ws + c * KS * KS;
        if (bank == 0)      conv_accum<3>(Xs, Wc, acc);
        else if (bank == 1) conv_accum<5>(Xs, Wc, acc);
        else                conv_accum<7>(Xs, Wc, acc);
    }

    float* outp = (src ? g_y : g_x) + (bank * 128 + l) * NPTS + b * 1024;
#pragma unroll
    for (int r = 0; r < 4; r++) outp[threadIdx.x + r * 256] = acc[r];
}

// ============================================================
// Stage 2 (fused, one block per filter, 512 threads):
//   tau (ddof=1 std of y) -> y-histogram (64 bins, centroids)
//   -> U_i for all 2048 x via weighted tanh
//   -> u-histogram (512 bins, fixed-point centroids)
//   -> Bernstein p_hat over u-bins -> f_js -> g_loss[f]
// All cross-thread accumulation is integer/fixed-point atomics
// or fixed-order reductions => bit-deterministic.
// ============================================================
__global__ void __launch_bounds__(512) fused_kernel() {
    int f = blockIdx.x;
    int t = threadIdx.x;

    __shared__ float  ys[NPTS];                       // 8KB
    __shared__ float  r1[16], r2[16], r3[16], r4[16];
    __shared__ float  bc[4];                          // c2, bmin, yscale, (pad)
    __shared__ int    ycnt[NHB];
    __shared__ unsigned long long ysum[NHB];
    __shared__ float2 hb[NHB];                        // (-c2*centroid, weight)
    __shared__ int    ucnt[NUB];
    __shared__ unsigned long long usum[NUB];
    __shared__ float  ulw[NUB], ul1[NUB], uw[NUB];
    __shared__ float  part[4][NBINS];
    __shared__ float  arr[NBINS];

    // init histograms
    for (int i = t; i < NHB; i += 512) { ycnt[i] = 0; ysum[i] = 0ull; }
    for (int i = t; i < NUB; i += 512) { ucnt[i] = 0; usum[i] = 0ull; }

    // ---- load y; accumulate sum/sumsq/min/max ----
    const float* y = g_y + f * NPTS;
    float s = 0.f, ss = 0.f, mn = 1e30f, mx = -1e30f;
    for (int i = t; i < NPTS; i += 512) {
        float v = y[i];
        ys[i] = v;
        s += v; ss = fmaf(v, v, ss);
        mn = fminf(mn, v); mx = fmaxf(mx, v);
    }
    for (int o = 16; o > 0; o >>= 1) {
        s  += __shfl_down_sync(0xffffffffu, s, o);
        ss += __shfl_down_sync(0xffffffffu, ss, o);
        mn  = fminf(mn, __shfl_down_sync(0xffffffffu, mn, o));
        mx  = fmaxf(mx, __shfl_down_sync(0xffffffffu, mx, o));
    }
    int w = t >> 5, lane = t & 31;
    if (lane == 0) { r1[w] = s; r2[w] = ss; r3[w] = mn; r4[w] = mx; }
    __syncthreads();

    if (t == 0) {
        float S = 0.f, SS = 0.f, MN = r3[0], MX = r4[0];
        for (int i = 0; i < 16; i++) {
            S += r1[i]; SS += r2[i];
            MN = fminf(MN, r3[i]); MX = fmaxf(MX, r4[i]);
        }
        float mean = S * (1.f / NPTS);
        float var  = (SS - (float)NPTS * mean * mean) * (1.f / (NPTS - 1));
        float sd   = sqrtf(fmaxf(var, 0.f));
        float scl  = (f < 128) ? 0.3f : (f < 256) ? 0.18f : 0.1f;
        float tau  = scl * (sd + 1e-6f) + 1e-4f;
        bc[0] = 0.5f / tau;                                   // c2
        bc[1] = MN;                                           // bmin
        bc[2] = (float)NHB / ((MX - MN) * (1.f + 1e-6f) + 1e-20f);  // yscale
    }
    __syncthreads();

    float c2 = bc[0], bmin = bc[1], yscale = bc[2];

    // ---- y histogram (fixed point: q in [0,NHB), scale 2^16) ----
    for (int i = t; i < NPTS; i += 512) {
        float q = (ys[i] - bmin) * yscale;
        int b = min((int)q, NHB - 1);
        atomicAdd(&ycnt[b], 1);
        atomicAdd(&ysum[b], (unsigned long long)(q * 65536.0f + 0.5f));
    }
    __syncthreads();

    for (int b = t; b < NHB; b += 512) {
        int c = ycnt[b];
        float cen = bmin;
        if (c > 0)
            cen = bmin + ((float)ysum[b] / (65536.0f * (float)c)) / yscale;
        hb[b] = make_float2(-c2 * cen, (float)c);
    }
    __syncthreads();

    // ---- U for 4 x-values per thread; u-histogram ----
    const float4 xv = ((const float4*)(g_x + f * NPTS))[t];
    float x0 = xv.x * c2, x1 = xv.y * c2, x2 = xv.z * c2, x3 = xv.w * c2;
    float a0 = 0.f, a1 = 0.f, a2 = 0.f, a3 = 0.f;
#pragma unroll 4
    for (int b = 0; b < NHB; b++) {
        float2 h = hb[b];
        a0 = fmaf(h.y, tanhf_approx(h.x + x0), a0);
        a1 = fmaf(h.y, tanhf_approx(h.x + x1), a1);
        a2 = fmaf(h.y, tanhf_approx(h.x + x2), a2);
        a3 = fmaf(h.y, tanhf_approx(h.x + x3), a3);
    }
#pragma unroll
    for (int q = 0; q < 4; q++) {
        float acc = (q == 0) ? a0 : (q == 1) ? a1 : (q == 2) ? a2 : a3;
        float u = fmaf(acc, 0.5f / NPTS, 0.5f);
        u = fminf(fmaxf(u, 1e-6f), 1.f - 1e-6f);
        int b = min((int)(u * (float)NUB), NUB - 1);
        atomicAdd(&ucnt[b], 1);
        atomicAdd(&usum[b], (unsigned long long)(u * 67108864.0f + 0.5f)); // 2^26
    }
    __syncthreads();

    // ---- per-u-bin log terms ----
    for (int b = t; b < NUB; b += 512) {
        int c = ucnt[b];
        if (c > 0) {
            float uc = (float)usum[b] / (67108864.0f * (float)c);
            uc = fminf(fmaxf(uc, 1e-6f), 1.f - 1e-6f);
            ulw[b] = logf(uc);
            ul1[b] = logf(1.f - uc);
            uw[b]  = (float)c;
        } else {
            ulw[b] = -40.f;   // sentinel: exp underflows to 0 (w=0 anyway)
            ul1[b] = -40.f;
            uw[b]  = 0.f;
        }
    }
    __syncthreads();

    // ---- Bernstein p_hat partials: 388 threads = 97 n x 4 chunks ----
    if (t < 4 * NBINS) {
        int n = t >> 2, ch = t & 3;
        float fn = (float)n, kn = (float)(KB - n);
        float logC = lgammaf((float)(KB + 1)) - lgammaf(fn + 1.f) - lgammaf(kn + 1.f);
        float acc = 0.f;
        int b0 = ch * (NUB / 4);
        for (int b = b0; b < b0 + NUB / 4; b++)
            acc += uw[b] * __expf(fmaf(fn, ulw[b], fmaf(kn, ul1[b], logC)));
        part[ch][n] = acc;
    }
    __syncthreads();

    // ---- f_js per bin, then serial deterministic block sum ----
    if (t < NBINS) {
        float p = part[0][t] + part[1][t] + part[2][t] + part[3][t];
        float ph = p * (1.f / NPTS);
        float v  = fmaxf(ph * (float)NBINS, 1e-12f);
        float wv = 1.f / (1.f + v);
        float term = 0.5f * (1.f + v) *
            (0.6931471805599453f + logf(fmaxf(wv, 1e-12f)) + log1pf(-wv));
        arr[t] = term * (1.f / NBINS);
    }
    __syncthreads();
    if (t == 0) {
        float acc = 0.f;
        for (int i = 0; i < NBINS; i++) acc += arr[i];
        g_loss[f] = acc;
    }
}

// ============================================================
// Stage 3: deterministic final reduction
// ============================================================
__global__ void __launch_bounds__(512) reduce_kernel(float* out) {
    int t = threadIdx.x;
    float v = (t < NFILT) ? g_loss[t] : 0.f;
    for (int o = 16; o > 0; o >>= 1) v += __shfl_down_sync(0xffffffffu, v, o);
    __shared__ float sh[16];
    if ((t & 31) == 0) sh[t >> 5] = v;
    __syncthreads();
    if (t == 0) {
        float s = 0.f;
        for (int i = 0; i < 16; i++) s += sh[i];
        out[0] = s * (1.f / 384.f);
    }
}

extern "C" void kernel_launch(void* const* d_in, const int* in_sizes, int n_in,
                              void* d_out, int out_size) {
    const float* Xg = (const float*)d_in[0];
    const float* Xd = (const float*)d_in[1];
    const float* W3 = (const float*)d_in[2];
    const float* W5 = (const float*)d_in[3];
    const float* W7 = (const float*)d_in[4];

    conv_kernel<<<1536, 256>>>(Xg, Xd, W3, W5, W7);
    fused_kernel<<<NFILT, 512>>>();
    reduce_kernel<<<1, 512>>>((float*)d_out);
}

// round 8
// speedup vs baseline: 10.6303x; 1.1416x over previous
#include <cuda_runtime.h>

#define NFILT 384      // 3 banks * 128 filters
#define NPTS  2048     // B*H'*W' = 2*32*32
#define KB    96
#define NBINS 97
#define NHB   64       // y-histogram bins (ECDF compression)
#define NUB   512      // u-histogram bins (Bernstein compression)

// ---- scratch (static device globals; no allocation anywhere) ----
__device__ float g_x[NFILT * NPTS];
__device__ float g_y[NFILT * NPTS];
__device__ float g_loss[NFILT];

__device__ __forceinline__ float tanhf_approx(float x) {
    float r; asm("tanh.approx.f32 %0, %1;" : "=f"(r) : "f"(x)); return r;
}

// ============================================================
// Stage 1: register-blocked direct conv, stride 2, zero pad.
// Block = (bank, src, batch, filter-group of 8); 256 thr x 4 pos.
// X tile in smem as even/odd column planes [72][2][36]:
//   col g (halo-shifted) -> plane g&1, offset g>>1.
//   A tap has fixed parity -> warp reads consecutive addresses
//   in one plane -> conflict-free despite stride-2 conv.
// Per tap: 8 weight LDS (broadcast) + 4 patch LDS -> 32 FMA.
// grid: 3 banks * 2 src * 2 batch * 16 groups = 192 blocks.
// ============================================================
template <int KS>
__device__ __forceinline__ void conv_group(
    const float* __restrict__ Xs, const float* __restrict__ Wsh,
    int wsz, int coff, const int* rowbase, float acc[4][8]) {
    const int P = KS / 2;
#pragma unroll
    for (int u = 0; u < KS; u++) {
#pragma unroll
        for (int v = 0; v < KS; v++) {
            int d   = v + 3 - P;
            int par = d & 1, dc = d >> 1;
            float wreg[8];
#pragma unroll
            for (int ff = 0; ff < 8; ff++)
                wreg[ff] = Wsh[ff * wsz + coff + u * KS + v];
#pragma unroll
            for (int r = 0; r < 4; r++) {
                float p = Xs[rowbase[r] + u * 72 + par * 36 + dc];
#pragma unroll
                for (int ff = 0; ff < 8; ff++)
                    acc[r][ff] = fmaf(wreg[ff], p, acc[r][ff]);
            }
        }
    }
}

__global__ void __launch_bounds__(256) conv_kernel(
    const float* __restrict__ Xg, const float* __restrict__ Xd,
    const float* __restrict__ W3, const float* __restrict__ W5,
    const float* __restrict__ W7) {
    __shared__ float Xs[72 * 72];       // [row][parity][36]
    __shared__ float Wsh[8 * 147];      // 8 filters x 3*KS*KS (max KS=7)

    int bx   = blockIdx.x;
    int bank = bx >> 6;          // 64 blocks per bank
    int rem  = bx & 63;
    int src  = rem >> 5;
    int b    = (rem >> 4) & 1;
    int grp  = rem & 15;         // 16 groups of 8 filters

    const float* X = (src ? Xd : Xg) + b * 12288;
    const float* W;
    int KS;
    if (bank == 0)      { W = W3; KS = 3; }
    else if (bank == 1) { W = W5; KS = 5; }
    else                { W = W7; KS = 7; }
    int wsz = 3 * KS * KS;
    int l0  = grp * 8;

    int t = threadIdx.x;
    for (int i = t; i < 8 * wsz; i += 256)
        Wsh[i] = W[(l0 + i / wsz) * wsz + (i % wsz)];
    for (int i = t; i < 72 * 72; i += 256) Xs[i] = 0.f;

    // per-thread position set and precomputed row bases
    int rowbase[4];
    int P = KS / 2;
    {
#pragma unroll
        for (int r = 0; r < 4; r++) {
            int idx = t + r * 256;
            int oy = idx >> 5, ox = idx & 31;
            rowbase[r] = (2 * oy + 3 - P) * 72 + ox;
        }
    }

    float acc[4][8];
#pragma unroll
    for (int r = 0; r < 4; r++)
#pragma unroll
        for (int ff = 0; ff < 8; ff++) acc[r][ff] = 0.f;

    for (int c = 0; c < 3; c++) {
        __syncthreads();
        for (int i = t; i < 4096; i += 256) {
            int gr = i >> 6, gc = i & 63;
            int g = gc + 3;
            Xs[(gr + 3) * 72 + (g & 1) * 36 + (g >> 1)] = X[c * 4096 + i];
        }
        __syncthreads();
        int coff = c * KS * KS;
        if (bank == 0)      conv_group<3>(Xs, Wsh, wsz, coff, rowbase, acc);
        else if (bank == 1) conv_group<5>(Xs, Wsh, wsz, coff, rowbase, acc);
        else                conv_group<7>(Xs, Wsh, wsz, coff, rowbase, acc);
    }

    float* outp = src ? g_y : g_x;
#pragma unroll
    for (int ff = 0; ff < 8; ff++) {
        int fg = bank * 128 + l0 + ff;
#pragma unroll
        for (int r = 0; r < 4; r++)
            outp[fg * NPTS + b * 1024 + t + r * 256] = acc[r][ff];
    }
}

// ============================================================
// Stage 2 (fused, one block per filter, 512 threads):
//   tau (ddof=1 std of y) -> y-histogram (64 bins, centroids)
//   -> U_i for all 2048 x via weighted tanh
//   -> u-histogram (512 bins, fixed-point centroids)
//   -> Bernstein p_hat over u-bins -> f_js -> g_loss[f]
// All cross-thread accumulation is integer/fixed-point atomics
// or fixed-order reductions => bit-deterministic.
// ============================================================
__global__ void __launch_bounds__(512) fused_kernel() {
    int f = blockIdx.x;
    int t = threadIdx.x;

    __shared__ float  ys[NPTS];                       // 8KB
    __shared__ float  r1[16], r2[16], r3[16], r4[16];
    __shared__ float  bc[4];                          // c2, bmin, yscale
    __shared__ int    ycnt[NHB];
    __shared__ unsigned long long ysum[NHB];
    __shared__ float2 hb[NHB];                        // (-c2*centroid, weight)
    __shared__ int    ucnt[NUB];
    __shared__ unsigned long long usum[NUB];
    __shared__ float  ulw[NUB], ul1[NUB], uw[NUB];
    __shared__ float  part[4][NBINS];
    __shared__ float  arr[NBINS];

    for (int i = t; i < NHB; i += 512) { ycnt[i] = 0; ysum[i] = 0ull; }
    for (int i = t; i < NUB; i += 512) { ucnt[i] = 0; usum[i] = 0ull; }

    // ---- load y; accumulate sum/sumsq/min/max ----
    const float* y = g_y + f * NPTS;
    float s = 0.f, ss = 0.f, mn = 1e30f, mx = -1e30f;
    for (int i = t; i < NPTS; i += 512) {
        float v = y[i];
        ys[i] = v;
        s += v; ss = fmaf(v, v, ss);
        mn = fminf(mn, v); mx = fmaxf(mx, v);
    }
    for (int o = 16; o > 0; o >>= 1) {
        s  += __shfl_down_sync(0xffffffffu, s, o);
        ss += __shfl_down_sync(0xffffffffu, ss, o);
        mn  = fminf(mn, __shfl_down_sync(0xffffffffu, mn, o));
        mx  = fmaxf(mx, __shfl_down_sync(0xffffffffu, mx, o));
    }
    int w = t >> 5, lane = t & 31;
    if (lane == 0) { r1[w] = s; r2[w] = ss; r3[w] = mn; r4[w] = mx; }
    __syncthreads();

    if (t == 0) {
        float S = 0.f, SS = 0.f, MN = r3[0], MX = r4[0];
        for (int i = 0; i < 16; i++) {
            S += r1[i]; SS += r2[i];
            MN = fminf(MN, r3[i]); MX = fmaxf(MX, r4[i]);
        }
        float mean = S * (1.f / NPTS);
        float var  = (SS - (float)NPTS * mean * mean) * (1.f / (NPTS - 1));
        float sd   = sqrtf(fmaxf(var, 0.f));
        float scl  = (f < 128) ? 0.3f : (f < 256) ? 0.18f : 0.1f;
        float tau  = scl * (sd + 1e-6f) + 1e-4f;
        bc[0] = 0.5f / tau;
        bc[1] = MN;
        bc[2] = (float)NHB / ((MX - MN) * (1.f + 1e-6f) + 1e-20f);
    }
    __syncthreads();

    float c2 = bc[0], bmin = bc[1], yscale = bc[2];

    // ---- y histogram (fixed point, scale 2^16) ----
    for (int i = t; i < NPTS; i += 512) {
        float q = (ys[i] - bmin) * yscale;
        int b = min((int)q, NHB - 1);
        atomicAdd(&ycnt[b], 1);
        atomicAdd(&ysum[b], (unsigned long long)(q * 65536.0f + 0.5f));
    }
    __syncthreads();

    for (int b = t; b < NHB; b += 512) {
        int c = ycnt[b];
        float cen = bmin;
        if (c > 0)
            cen = bmin + ((float)ysum[b] / (65536.0f * (float)c)) / yscale;
        hb[b] = make_float2(-c2 * cen, (float)c);
    }
    __syncthreads();

    // ---- U for 4 x-values per thread; u-histogram ----
    const float4 xv = ((const float4*)(g_x + f * NPTS))[t];
    float x0 = xv.x * c2, x1 = xv.y * c2, x2 = xv.z * c2, x3 = xv.w * c2;
    float a0 = 0.f, a1 = 0.f, a2 = 0.f, a3 = 0.f;
#pragma unroll 4
    for (int b = 0; b < NHB; b++) {
        float2 h = hb[b];
        a0 = fmaf(h.y, tanhf_approx(h.x + x0), a0);
        a1 = fmaf(h.y, tanhf_approx(h.x + x1), a1);
        a2 = fmaf(h.y, tanhf_approx(h.x + x2), a2);
        a3 = fmaf(h.y, tanhf_approx(h.x + x3), a3);
    }
#pragma unroll
    for (int q = 0; q < 4; q++) {
        float acc = (q == 0) ? a0 : (q == 1) ? a1 : (q == 2) ? a2 : a3;
        float u = fmaf(acc, 0.5f / NPTS, 0.5f);
        u = fminf(fmaxf(u, 1e-6f), 1.f - 1e-6f);
        int b = min((int)(u * (float)NUB), NUB - 1);
        atomicAdd(&ucnt[b], 1);
        atomicAdd(&usum[b], (unsigned long long)(u * 67108864.0f + 0.5f)); // 2^26
    }
    __syncthreads();

    // ---- per-u-bin log terms ----
    for (int b = t; b < NUB; b += 512) {
        int c = ucnt[b];
        if (c > 0) {
            float uc = (float)usum[b] / (67108864.0f * (float)c);
            uc = fminf(fmaxf(uc, 1e-6f), 1.f - 1e-6f);
            ulw[b] = logf(uc);
            ul1[b] = logf(1.f - uc);
            uw[b]  = (float)c;
        } else {
            ulw[b] = -40.f;
            ul1[b] = -40.f;
            uw[b]  = 0.f;
        }
    }
    __syncthreads();

    // ---- Bernstein p_hat partials: 388 threads = 97 n x 4 chunks ----
    if (t < 4 * NBINS) {
        int n = t >> 2, ch = t & 3;
        float fn = (float)n, kn = (float)(KB - n);
        float logC = lgammaf((float)(KB + 1)) - lgammaf(fn + 1.f) - lgammaf(kn + 1.f);
        float acc = 0.f;
        int b0 = ch * (NUB / 4);
        for (int b = b0; b < b0 + NUB / 4; b++)
            acc += uw[b] * __expf(fmaf(fn, ulw[b], fmaf(kn, ul1[b], logC)));
        part[ch][n] = acc;
    }
    __syncthreads();

    // ---- f_js per bin, then serial deterministic block sum ----
    if (t < NBINS) {
        float p = part[0][t] + part[1][t] + part[2][t] + part[3][t];
        float ph = p * (1.f / NPTS);
        float v  = fmaxf(ph * (float)NBINS, 1e-12f);
        float wv = 1.f / (1.f + v);
        float term = 0.5f * (1.f + v) *
            (0.6931471805599453f + logf(fmaxf(wv, 1e-12f)) + log1pf(-wv));
        arr[t] = term * (1.f / NBINS);
    }
    __syncthreads();
    if (t == 0) {
        float acc = 0.f;
        for (int i = 0; i < NBINS; i++) acc += arr[i];
        g_loss[f] = acc;
    }
}

// ============================================================
// Stage 3: deterministic final reduction
// ============================================================
__global__ void __launch_bounds__(512) reduce_kernel(float* out) {
    int t = threadIdx.x;
    float v = (t < NFILT) ? g_loss[t] : 0.f;
    for (int o = 16; o > 0; o >>= 1) v += __shfl_down_sync(0xffffffffu, v, o);
    __shared__ float sh[16];
    if ((t & 31) == 0) sh[t >> 5] = v;
    __syncthreads();
    if (t == 0) {
        float s = 0.f;
        for (int i = 0; i < 16; i++) s += sh[i];
        out[0] = s * (1.f / 384.f);
    }
}

extern "C" void kernel_launch(void* const* d_in, const int* in_sizes, int n_in,
                              void* d_out, int out_size) {
    const float* Xg = (const float*)d_in[0];
    const float* Xd = (const float*)d_in[1];
    const float* W3 = (const float*)d_in[2];
    const float* W5 = (const float*)d_in[3];
    const float* W7 = (const float*)d_in[4];

    conv_kernel<<<192, 256>>>(Xg, Xd, W3, W5, W7);
    fused_kernel<<<NFILT, 512>>>();
    reduce_kernel<<<1, 512>>>((float*)d_out);
}

// round 9
// speedup vs baseline: 12.9227x; 1.2156x over previous
#include <cuda_runtime.h>

#define NFILT 384      // 3 banks * 128 filters
#define NPTS  2048     // B*H'*W' = 2*32*32
#define KB    96
#define NBINS 97
#define NHB   64       // y-histogram bins (ECDF compression)
#define NUB   512      // u-histogram bins (Bernstein compression)

// ---- scratch (static device globals; no allocation anywhere) ----
__device__ float g_x[NFILT * NPTS];
__device__ float g_y[NFILT * NPTS];
__device__ float g_loss[NFILT];

__device__ __forceinline__ float tanhf_approx(float x) {
    float r; asm("tanh.approx.f32 %0, %1;" : "=f"(r) : "f"(x)); return r;
}

// ============================================================
// Stage 1: register-blocked direct conv, stride 2, zero pad.
// Block = (bank, src, batch, filter-group of 4); 256 thr x 4 pos.
// X tile in smem as even/odd column planes [72][2][36] ->
// conflict-free stride-2 taps. Per tap: 4 wgt + 4 patch LDS -> 16 FMA.
// grid: 3 banks * 2 src * 2 batch * 32 groups = 384 blocks.
// ============================================================
template <int KS>
__device__ __forceinline__ void conv_group(
    const float* __restrict__ Xs, const float* __restrict__ Wsh,
    int wsz, int coff, const int* rowbase, float acc[4][4]) {
    const int P = KS / 2;
#pragma unroll
    for (int u = 0; u < KS; u++) {
#pragma unroll
        for (int v = 0; v < KS; v++) {
            int d   = v + 3 - P;
            int par = d & 1, dc = d >> 1;
            float wreg[4];
#pragma unroll
            for (int ff = 0; ff < 4; ff++)
                wreg[ff] = Wsh[ff * wsz + coff + u * KS + v];
#pragma unroll
            for (int r = 0; r < 4; r++) {
                float p = Xs[rowbase[r] + u * 72 + par * 36 + dc];
#pragma unroll
                for (int ff = 0; ff < 4; ff++)
                    acc[r][ff] = fmaf(wreg[ff], p, acc[r][ff]);
            }
        }
    }
}

__global__ void __launch_bounds__(256) conv_kernel(
    const float* __restrict__ Xg, const float* __restrict__ Xd,
    const float* __restrict__ W3, const float* __restrict__ W5,
    const float* __restrict__ W7) {
    __shared__ float Xs[72 * 72];       // [row][parity][36]
    __shared__ float Wsh[4 * 147];      // 4 filters x 3*KS*KS (max KS=7)

    int bx   = blockIdx.x;
    int bank = bx >> 7;          // 128 blocks per bank
    int rem  = bx & 127;
    int src  = rem >> 6;
    int b    = (rem >> 5) & 1;
    int grp  = rem & 31;         // 32 groups of 4 filters

    const float* X = (src ? Xd : Xg) + b * 12288;
    const float* W;
    int KS;
    if (bank == 0)      { W = W3; KS = 3; }
    else if (bank == 1) { W = W5; KS = 5; }
    else                { W = W7; KS = 7; }
    int wsz = 3 * KS * KS;
    int l0  = grp * 4;

    int t = threadIdx.x;
    for (int i = t; i < 4 * wsz; i += 256)
        Wsh[i] = W[(l0 + i / wsz) * wsz + (i % wsz)];
    for (int i = t; i < 72 * 72; i += 256) Xs[i] = 0.f;

    int rowbase[4];
    int P = KS / 2;
#pragma unroll
    for (int r = 0; r < 4; r++) {
        int idx = t + r * 256;
        int oy = idx >> 5, ox = idx & 31;
        rowbase[r] = (2 * oy + 3 - P) * 72 + ox;
    }

    float acc[4][4];
#pragma unroll
    for (int r = 0; r < 4; r++)
#pragma unroll
        for (int ff = 0; ff < 4; ff++) acc[r][ff] = 0.f;

    for (int c = 0; c < 3; c++) {
        __syncthreads();
        for (int i = t; i < 4096; i += 256) {
            int gr = i >> 6, gc = i & 63;
            int g = gc + 3;
            Xs[(gr + 3) * 72 + (g & 1) * 36 + (g >> 1)] = X[c * 4096 + i];
        }
        __syncthreads();
        int coff = c * KS * KS;
        if (bank == 0)      conv_group<3>(Xs, Wsh, wsz, coff, rowbase, acc);
        else if (bank == 1) conv_group<5>(Xs, Wsh, wsz, coff, rowbase, acc);
        else                conv_group<7>(Xs, Wsh, wsz, coff, rowbase, acc);
    }

    float* outp = src ? g_y : g_x;
#pragma unroll
    for (int ff = 0; ff < 4; ff++) {
        int fg = bank * 128 + l0 + ff;
#pragma unroll
        for (int r = 0; r < 4; r++)
            outp[fg * NPTS + b * 1024 + t + r * 256] = acc[r][ff];
    }
}

// ============================================================
// Stage 2 (fused, one block per filter, 512 threads):
//   tau -> y-histogram (64 bins, centroids, uint32 fixed-point)
//   -> U via weighted tanh -> u-histogram (512 bins, uint32)
//   -> Bernstein p_hat -> f_js -> g_loss[f]
// Integer atomics + fixed-order reductions => bit-deterministic.
// ============================================================
__global__ void __launch_bounds__(512) fused_kernel() {
    int f = blockIdx.x;
    int t = threadIdx.x;

    __shared__ float  ys[NPTS];                       // 8KB
    __shared__ float  r1[16], r2[16], r3[16], r4[16];
    __shared__ float  bc[4];                          // c2, bmin, yscale
    __shared__ unsigned ycnt[NHB], ysum[NHB];         // sum scale 2^14
    __shared__ float2 hb[NHB];                        // (-c2*centroid, weight)
    __shared__ unsigned ucnt[NUB], usum[NUB];         // sum scale 2^20
    __shared__ float  ulw[NUB], ul1[NUB], uw[NUB];
    __shared__ float  part[4][NBINS];
    __shared__ float  arr[128];

    for (int i = t; i < NHB; i += 512) { ycnt[i] = 0u; ysum[i] = 0u; }
    for (int i = t; i < NUB; i += 512) { ucnt[i] = 0u; usum[i] = 0u; }

    // ---- load y; accumulate sum/sumsq/min/max ----
    const float* y = g_y + f * NPTS;
    float s = 0.f, ss = 0.f, mn = 1e30f, mx = -1e30f;
    for (int i = t; i < NPTS; i += 512) {
        float v = y[i];
        ys[i] = v;
        s += v; ss = fmaf(v, v, ss);
        mn = fminf(mn, v); mx = fmaxf(mx, v);
    }
    for (int o = 16; o > 0; o >>= 1) {
        s  += __shfl_down_sync(0xffffffffu, s, o);
        ss += __shfl_down_sync(0xffffffffu, ss, o);
        mn  = fminf(mn, __shfl_down_sync(0xffffffffu, mn, o));
        mx  = fmaxf(mx, __shfl_down_sync(0xffffffffu, mx, o));
    }
    int w = t >> 5, lane = t & 31;
    if (lane == 0) { r1[w] = s; r2[w] = ss; r3[w] = mn; r4[w] = mx; }
    __syncthreads();

    if (t == 0) {
        float S = 0.f, SS = 0.f, MN = r3[0], MX = r4[0];
        for (int i = 0; i < 16; i++) {
            S += r1[i]; SS += r2[i];
            MN = fminf(MN, r3[i]); MX = fmaxf(MX, r4[i]);
        }
        float mean = S * (1.f / NPTS);
        float var  = (SS - (float)NPTS * mean * mean) * (1.f / (NPTS - 1));
        float sd   = sqrtf(fmaxf(var, 0.f));
        float scl  = (f < 128) ? 0.3f : (f < 256) ? 0.18f : 0.1f;
        float tau  = scl * (sd + 1e-6f) + 1e-4f;
        bc[0] = 0.5f / tau;
        bc[1] = MN;
        bc[2] = (float)NHB / ((MX - MN) * (1.f + 1e-6f) + 1e-20f);
    }
    __syncthreads();

    float c2 = bc[0], bmin = bc[1], yscale = bc[2];

    // ---- y histogram (uint32 fixed point, q scale 2^14) ----
    for (int i = t; i < NPTS; i += 512) {
        float q = (ys[i] - bmin) * yscale;
        int b = min((int)q, NHB - 1);
        atomicAdd(&ycnt[b], 1u);
        atomicAdd(&ysum[b], (unsigned)(q * 16384.0f + 0.5f));
    }
    __syncthreads();

    for (int b = t; b < NHB; b += 512) {
        unsigned c = ycnt[b];
        float cen = bmin;
        if (c > 0)
            cen = bmin + ((float)ysum[b] / (16384.0f * (float)c)) / yscale;
        hb[b] = make_float2(-c2 * cen, (float)c);
    }
    __syncthreads();

    // ---- U for 4 x-values per thread; u-histogram ----
    const float4 xv = ((const float4*)(g_x + f * NPTS))[t];
    float x0 = xv.x * c2, x1 = xv.y * c2, x2 = xv.z * c2, x3 = xv.w * c2;
    float a0 = 0.f, a1 = 0.f, a2 = 0.f, a3 = 0.f;
#pragma unroll 4
    for (int b = 0; b < NHB; b++) {
        float2 h = hb[b];
        a0 = fmaf(h.y, tanhf_approx(h.x + x0), a0);
        a1 = fmaf(h.y, tanhf_approx(h.x + x1), a1);
        a2 = fmaf(h.y, tanhf_approx(h.x + x2), a2);
        a3 = fmaf(h.y, tanhf_approx(h.x + x3), a3);
    }
#pragma unroll
    for (int q = 0; q < 4; q++) {
        float acc = (q == 0) ? a0 : (q == 1) ? a1 : (q == 2) ? a2 : a3;
        float u = fmaf(acc, 0.5f / NPTS, 0.5f);
        u = fminf(fmaxf(u, 1e-6f), 1.f - 1e-6f);
        int b = min((int)(u * (float)NUB), NUB - 1);
        atomicAdd(&ucnt[b], 1u);
        atomicAdd(&usum[b], (unsigned)(u * 1048576.0f + 0.5f));  // 2^20
    }
    __syncthreads();

    // ---- per-u-bin log terms ----
    for (int b = t; b < NUB; b += 512) {
        unsigned c = ucnt[b];
        if (c > 0) {
            float uc = (float)usum[b] / (1048576.0f * (float)c);
            uc = fminf(fmaxf(uc, 1e-6f), 1.f - 1e-6f);
            ulw[b] = logf(uc);
            ul1[b] = logf(1.f - uc);
            uw[b]  = (float)c;
        } else {
            ulw[b] = -40.f;
            ul1[b] = -40.f;
            uw[b]  = 0.f;
        }
    }
    __syncthreads();

    // ---- Bernstein p_hat partials: 388 threads = 97 n x 4 chunks ----
    if (t < 4 * NBINS) {
        int n = t >> 2, ch = t & 3;
        float fn = (float)n, kn = (float)(KB - n);
        float logC = lgammaf((float)(KB + 1)) - lgammaf(fn + 1.f) - lgammaf(kn + 1.f);
        float acc = 0.f;
        int b0 = ch * (NUB / 4);
        for (int b = b0; b < b0 + NUB / 4; b++)
            acc += uw[b] * __expf(fmaf(fn, ulw[b], fmaf(kn, ul1[b], logC)));
        part[ch][n] = acc;
    }
    __syncthreads();

    // ---- f_js per bin, then fixed-order parallel block sum ----
    float val = 0.f;
    if (t < NBINS) {
        float p = part[0][t] + part[1][t] + part[2][t] + part[3][t];
        float ph = p * (1.f / NPTS);
        float v  = fmaxf(ph * (float)NBINS, 1e-12f);
        float wv = 1.f / (1.f + v);
        float term = 0.5f * (1.f + v) *
            (0.6931471805599453f + logf(fmaxf(wv, 1e-12f)) + log1pf(-wv));
        val = term * (1.f / NBINS);
    }
    if (t < 128) arr[t] = (t < NBINS) ? val : 0.f;
    __syncthreads();
    if (t < 32) {
        float a = arr[t] + arr[t + 32] + arr[t + 64] + arr[t + 96];
        for (int o = 16; o > 0; o >>= 1)
            a += __shfl_down_sync(0xffffffffu, a, o);
        if (t == 0) g_loss[f] = a;
    }
}

// ============================================================
// Stage 3: deterministic final reduction
// ============================================================
__global__ void __launch_bounds__(512) reduce_kernel(float* out) {
    int t = threadIdx.x;
    float v = (t < NFILT) ? g_loss[t] : 0.f;
    for (int o = 16; o > 0; o >>= 1) v += __shfl_down_sync(0xffffffffu, v, o);
    __shared__ float sh[16];
    if ((t & 31) == 0) sh[t >> 5] = v;
    __syncthreads();
    if (t == 0) {
        float s = 0.f;
        for (int i = 0; i < 16; i++) s += sh[i];
        out[0] = s * (1.f / 384.f);
    }
}

extern "C" void kernel_launch(void* const* d_in, const int* in_sizes, int n_in,
                              void* d_out, int out_size) {
    const float* Xg = (const float*)d_in[0];
    const float* Xd = (const float*)d_in[1];
    const float* W3 = (const float*)d_in[2];
    const float* W5 = (const float*)d_in[3];
    const float* W7 = (const float*)d_in[4];

    conv_kernel<<<384, 256>>>(Xg, Xd, W3, W5, W7);
    fused_kernel<<<NFILT, 512>>>();
    reduce_kernel<<<1, 512>>>((float*)d_out);
}